// round 17
// baseline (speedup 1.0000x reference)
#include <cuda_runtime.h>
#include <cuda_fp16.h>
#include <mma.h>
#include <math.h>
#include <cstdint>

using namespace nvcuda;

#define B_   2
#define S_   2048
#define H_   1024
#define NH_  16
#define HD_  64
#define MR_  (B_ * S_)
#define ATTN_SCALE 0.125f

// ---------------- scratch (half everywhere on the MMA paths) -----------------
__device__ __half g_x_h[MR_ * H_];           // fp16 x            [M][K]
__device__ __half g_wqkv_h[H_ * 3 * H_];     // fp16 w_qkv        [K][N]
__device__ __half g_wout_h[H_ * H_];         // fp16 w_out        [K][N]
__device__ __half g_q[B_ * NH_ * S_ * HD_];  // (b,h,s,d) q pre-scaled
__device__ __half g_k[B_ * NH_ * S_ * HD_];
__device__ __half g_v[B_ * NH_ * S_ * HD_];
__device__ __half g_att[MR_ * H_];           // (b,s,H)

// ---------------- cp.async helpers ------------------------------------------
__device__ __forceinline__ unsigned smem_u32(const void* p) {
    return (unsigned)__cvta_generic_to_shared(p);
}
#define CP_ASYNC16(dst_u32, src_ptr) \
    asm volatile("cp.async.cg.shared.global [%0], [%1], 16;\n" :: "r"(dst_u32), "l"(src_ptr))
#define CP_COMMIT() asm volatile("cp.async.commit_group;\n" ::)
#define CP_WAIT(N)  asm volatile("cp.async.wait_group %0;\n" :: "n"(N))
// pair-local named barrier: 64 threads (warps 2p, 2p+1), ids 1..8
#define PAIR_BAR(p) asm volatile("bar.sync %0, 64;" :: "r"(1 + (p)) : "memory")

// ---------------- prep: fused fp32 -> fp16 conversion ------------------------
#define N4_X  (MR_ * H_ / 4)
#define N4_WQ (H_ * 3 * H_ / 4)
#define N4_WO (H_ * H_ / 4)
#define N4_TOTAL (N4_X + N4_WQ + N4_WO)

__global__ void tohalf_all_kernel(const float4* __restrict__ x,
                                  const float4* __restrict__ wqkv,
                                  const float4* __restrict__ wout)
{
    int i = blockIdx.x * blockDim.x + threadIdx.x;
    const float4* src;
    __half2* dst;
    int j;
    if (i < N4_X)              { src = x;    dst = (__half2*)g_x_h;    j = i; }
    else if (i < N4_X + N4_WQ) { src = wqkv; dst = (__half2*)g_wqkv_h; j = i - N4_X; }
    else if (i < N4_TOTAL)     { src = wout; dst = (__half2*)g_wout_h; j = i - N4_X - N4_WQ; }
    else return;
    float4 v = src[j];
    dst[2 * j]     = __floats2half2_rn(v.x, v.y);
    dst[2 * j + 1] = __floats2half2_rn(v.z, v.w);
}

// ---------------- fp16 wmma GEMM (unchanged from R15: BK=64) -----------------
#define BM 128
#define BN 128
#define BK 64
#define LDA_H 80
#define LDB_H 144
#define A_STAGE_H (BM * LDA_H)
#define B_STAGE_H (BK * LDB_H)
#define GEMM_SMEM ((2 * A_STAGE_H + 2 * B_STAGE_H) * 2)

template <int EPI>
__global__ __launch_bounds__(128) void gemm_fp16_kernel(
    const float* __restrict__ bias, float* __restrict__ C,
    int M, int N, int K)
{
    const __half* A  = (EPI == 1) ? (const __half*)g_att    : (const __half*)g_x_h;
    const __half* Bw = (EPI == 1) ? (const __half*)g_wout_h : (const __half*)g_wqkv_h;

    extern __shared__ __half smh[];
    __half* As = smh;
    __half* Bs = smh + 2 * A_STAGE_H;

    const int bm   = blockIdx.y * BM;
    const int bn   = blockIdx.x * BN;
    const int tid  = threadIdx.x;
    const int warp = tid >> 5;
    const int lane = tid & 31;
    const int wm   = warp >> 1;
    const int wn   = warp & 1;

    wmma::fragment<wmma::accumulator, 16, 16, 16, float> acc[4][4];
#pragma unroll
    for (int i = 0; i < 4; i++)
#pragma unroll
        for (int j = 0; j < 4; j++) wmma::fill_fragment(acc[i][j], 0.0f);

    const int NIT = K / BK;

    auto load_stage = [&](int st, int k0) {
#pragma unroll
        for (int it = 0; it < 8; it++) {
            int idx = tid + it * 128;
            int r   = idx >> 3;
            int c8  = (idx & 7) << 3;
            CP_ASYNC16(smem_u32(&As[st * A_STAGE_H + r * LDA_H + c8]),
                       &A[(size_t)(bm + r) * K + k0 + c8]);
        }
#pragma unroll
        for (int it = 0; it < 8; it++) {
            int idx = tid + it * 128;
            int r   = idx >> 4;
            int c8  = (idx & 15) << 3;
            CP_ASYNC16(smem_u32(&Bs[st * B_STAGE_H + r * LDB_H + c8]),
                       &Bw[(size_t)(k0 + r) * N + bn + c8]);
        }
    };

    load_stage(0, 0);
    CP_COMMIT();

    for (int it = 0; it < NIT; it++) {
        if (it + 1 < NIT) {
            load_stage((it + 1) & 1, (it + 1) * BK);
            CP_COMMIT();
            CP_WAIT(1);
        } else {
            CP_WAIT(0);
        }
        __syncthreads();

        const __half* Ac = &As[(it & 1) * A_STAGE_H];
        const __half* Bc = &Bs[(it & 1) * B_STAGE_H];
#pragma unroll
        for (int kk = 0; kk < BK / 16; kk++) {
            wmma::fragment<wmma::matrix_a, 16, 16, 16, __half, wmma::row_major> af[4];
            wmma::fragment<wmma::matrix_b, 16, 16, 16, __half, wmma::row_major> bf[4];
#pragma unroll
            for (int i = 0; i < 4; i++)
                wmma::load_matrix_sync(af[i], &Ac[(wm * 64 + i * 16) * LDA_H + kk * 16], LDA_H);
#pragma unroll
            for (int j = 0; j < 4; j++)
                wmma::load_matrix_sync(bf[j], &Bc[(kk * 16) * LDB_H + wn * 64 + j * 16], LDB_H);
#pragma unroll
            for (int i = 0; i < 4; i++)
#pragma unroll
                for (int j = 0; j < 4; j++)
                    wmma::mma_sync(acc[i][j], af[i], bf[j], acc[i][j]);
        }
        __syncthreads();
    }

    float* scr = (float*)smh + warp * 16 * 20;
#pragma unroll
    for (int i = 0; i < 4; i++) {
#pragma unroll
        for (int j = 0; j < 4; j++) {
            wmma::store_matrix_sync(scr, acc[i][j], 20, wmma::mem_row_major);
            __syncwarp();
#pragma unroll
            for (int e = 0; e < 8; e++) {
                int idx = lane + e * 32;
                int rr = idx >> 4, cc = idx & 15;
                int m = bm + wm * 64 + i * 16 + rr;
                int n = bn + wn * 64 + j * 16 + cc;
                float val = scr[rr * 20 + cc] + bias[n];
                if (EPI == 0) {
                    int which = n >> 10;           // 0=q 1=k 2=v
                    int hn = n & (H_ - 1);
                    int h  = hn >> 6;
                    int d  = hn & (HD_ - 1);
                    int bb = m >> 11;
                    int s  = m & (S_ - 1);
                    if (which == 0) val *= ATTN_SCALE;
                    size_t dst = ((size_t)(bb * NH_ + h) * S_ + s) * HD_ + d;
                    __half* T = (which == 0) ? g_q : (which == 1) ? g_k : g_v;
                    T[dst] = __float2half_rn(val);
                } else {
                    C[(size_t)m * N + n] = val;
                }
            }
            __syncwarp();
        }
    }
}

// ---------------- fp16 wmma attention: 128-row Q tile, 16 warps, pair-split --
// R13 layout scaled 2x: 8 pairs x 16 rows = 128 query rows; pair p owns
// S/P rows p*16..+16; wc = col half (per-warp fragment loads SAME as R13 —
// this preserves the pair-split smem economics R16 broke). KV streams once
// per 128 queries: half the [A] barriers / prologues / KV traffic per work.
#define QROWS 128
#define LDS_KV 80
#define KV_ST (64 * LDS_KV)              // halves per stage per tensor
#define PH_STRIDE (16 * LDS_KV)          // per-pair P strip
#define PH_HALVES (8 * PH_STRIDE)        // 128 rows
#define LDS_OF 72
#define ATTN_SMEM ((4 * KV_ST + PH_HALVES) * 2 + 128 * 4 + 128)   // ~62 KB

__global__ __launch_bounds__(512) void attn_fp16_kernel()
{
    extern __shared__ __half smh[];
    __half* Ks = smh;                        // [2][64][LDS_KV]
    __half* Vs = smh + 2 * KV_ST;            // [2][64][LDS_KV]
    __half* Pw = smh + 4 * KV_ST;            // [8][16][LDS_KV] pair strips (Q then P)
    float*  l_s = (float*)(Pw + PH_HALVES);  // [128]
    float*  Of  = (float*)smh;               // O staging after loop (Ks/Vs dead)

    const int qt = blockIdx.x;               // 0..15 (128-row Q tiles)
    const int bh = blockIdx.y;
    const __half* Qb = g_q + (size_t)bh * S_ * HD_;
    const __half* Kb = g_k + (size_t)bh * S_ * HD_;
    const __half* Vb = g_v + (size_t)bh * S_ * HD_;

    const int tid  = threadIdx.x;
    const int warp = tid >> 5;
    const int pair = warp >> 1;              // 0..7 (rows pair*16..+16)
    const int wc   = warp & 1;               // col half 0/1
    const int pt   = tid & 63;               // thread index within pair
    const int prow = pair * 16 + (pt >> 2);  // this thread's P row (0..127)
    const int pcol0 = (pt & 3) << 4;         // 16-col chunk base
    __half* Ph = Pw + pair * PH_STRIDE;      // pair's 16x64 strip
    const int wrow0 = qt * QROWS + pair * 16;    // first global row of strip

    auto load_kv = [&](int st, int kt) {
        int r  = tid >> 3;                   // 512 threads -> 512 chunks (64 x 8)
        int c8 = (tid & 7) << 3;
        size_t src = (size_t)(kt * 64 + r) * HD_ + c8;
        CP_ASYNC16(smem_u32(&Ks[st * KV_ST + r * LDS_KV + c8]), &Kb[src]);
        CP_ASYNC16(smem_u32(&Vs[st * KV_ST + r * LDS_KV + c8]), &Vb[src]);
    };

    const int kt0 = qt * 2;
    const int nkt = S_ / 64 - kt0;           // >= 2

    load_kv(0, kt0);
    CP_COMMIT();

    // stage Q rows qt*128..+128 into pair strips (strips contiguous by row)
#pragma unroll
    for (int it = 0; it < 2; it++) {
        int idx = tid + it * 512;            // 0..1023
        int r   = idx >> 3;
        int c8  = (idx & 7) << 3;
        *reinterpret_cast<uint4*>(&Pw[r * LDS_KV + c8]) =
            *reinterpret_cast<const uint4*>(&Qb[(size_t)(qt * QROWS + r) * HD_ + c8]);
    }
    if (tid < 128) l_s[tid] = 0.0f;
    __syncthreads();

    wmma::fragment<wmma::matrix_a, 16, 16, 16, __half, wmma::row_major> qf[4];
#pragma unroll
    for (int kk = 0; kk < 4; kk++)
        wmma::load_matrix_sync(qf[kk], &Ph[kk * 16], LDS_KV);

    wmma::fragment<wmma::accumulator, 16, 16, 16, float> o_acc[2];
    wmma::fill_fragment(o_acc[0], 0.0f);
    wmma::fill_fragment(o_acc[1], 0.0f);
    // first in-loop [A] (block-wide) orders qf loads before Ph is reused for P

    for (int i = 0; i < nkt; i++) {
        const int kt = kt0 + i;
        CP_WAIT(0);
        __syncthreads();                     // [A] block-wide: KV stage i visible
        if (i + 1 < nkt) {
            load_kv((i + 1) & 1, kt + 1);    // overlaps this tile's compute
            CP_COMMIT();
        }
        const __half* Kc = &Ks[(i & 1) * KV_ST];
        const __half* Vc = &Vs[(i & 1) * KV_ST];

        if (kt * 64 + 63 < wrow0) continue;  // tile fully masked for this pair

        // S = Q @ K^T  (pair rows x pair's col half)
        wmma::fragment<wmma::accumulator, 16, 16, 16, float> s_acc[2];
        wmma::fill_fragment(s_acc[0], 0.0f);
        wmma::fill_fragment(s_acc[1], 0.0f);
#pragma unroll
        for (int kk = 0; kk < 4; kk++) {
            wmma::fragment<wmma::matrix_b, 16, 16, 16, __half, wmma::col_major> kf[2];
#pragma unroll
            for (int j = 0; j < 2; j++)
                wmma::load_matrix_sync(kf[j], &Kc[(wc * 32 + j * 16) * LDS_KV + kk * 16], LDS_KV);
            wmma::mma_sync(s_acc[0], qf[kk], kf[0], s_acc[0]);
            wmma::mma_sync(s_acc[1], qf[kk], kf[1], s_acc[1]);
        }

        // exp + fp16 convert IN REGISTER
        wmma::fragment<wmma::accumulator, 16, 16, 16, __half> p_h[2];
#pragma unroll
        for (int t = 0; t < s_acc[0].num_elements; t++) {
            p_h[0].x[t] = __float2half_rn(__expf(s_acc[0].x[t]));
            p_h[1].x[t] = __float2half_rn(__expf(s_acc[1].x[t]));
        }
        wmma::store_matrix_sync(&Ph[wc * 32],      p_h[0], LDS_KV, wmma::mem_row_major);
        wmma::store_matrix_sync(&Ph[wc * 32 + 16], p_h[1], LDS_KV, wmma::mem_row_major);
        PAIR_BAR(pair);                      // [B] pair-local: P strip visible

        if (kt * 64 < wrow0 + 16) {
            // diagonal tile for this pair: zero masked entries + sum (+1 bar)
            int grow = qt * QROWS + prow;
            int gc0  = kt * 64 + pcol0;
            float part = 0.0f;
#pragma unroll
            for (int c = 0; c < 16; c++) {
                __half hp = Ph[(pt >> 2) * LDS_KV + pcol0 + c];
                if (gc0 + c < grow) {
                    hp = __ushort_as_half((unsigned short)0);
                    Ph[(pt >> 2) * LDS_KV + pcol0 + c] = hp;
                }
                part += __half2float(hp);
            }
            part += __shfl_xor_sync(0xffffffffu, part, 1);
            part += __shfl_xor_sync(0xffffffffu, part, 2);
            if ((pt & 3) == 0) l_s[prow] += part;
            PAIR_BAR(pair);                  // masked P visible before PV
        } else {
            // fast path: read-only row sums (concurrent with PV loads)
            float part = 0.0f;
            const __half2* pp = (const __half2*)&Ph[(pt >> 2) * LDS_KV + pcol0];
#pragma unroll
            for (int c = 0; c < 8; c++) {
                float2 f = __half22float2(pp[c]);
                part += f.x + f.y;
            }
            part += __shfl_xor_sync(0xffffffffu, part, 1);
            part += __shfl_xor_sync(0xffffffffu, part, 2);
            if ((pt & 3) == 0) l_s[prow] += part;
            // no bar: PV also only reads Ph; next write ordered by [A]
        }

        // O += P @ V  (pf reads this pair's 16 rows of P)
#pragma unroll
        for (int kk = 0; kk < 4; kk++) {
            wmma::fragment<wmma::matrix_a, 16, 16, 16, __half, wmma::row_major> pf;
            wmma::load_matrix_sync(pf, &Ph[kk * 16], LDS_KV);
            wmma::fragment<wmma::matrix_b, 16, 16, 16, __half, wmma::row_major> vf[2];
#pragma unroll
            for (int j = 0; j < 2; j++)
                wmma::load_matrix_sync(vf[j], &Vc[(kk * 16) * LDS_KV + wc * 32 + j * 16], LDS_KV);
            wmma::mma_sync(o_acc[0], pf, vf[0], o_acc[0]);
            wmma::mma_sync(o_acc[1], pf, vf[1], o_acc[1]);
        }
        // no tail sync: next iteration's [A] covers reuse
    }
    __syncthreads();   // loop done; Ks/Vs dead -> reuse as float O staging

    float* Ow = Of + pair * 16 * LDS_OF;
    wmma::store_matrix_sync(&Ow[wc * 32],      o_acc[0], LDS_OF, wmma::mem_row_major);
    wmma::store_matrix_sync(&Ow[wc * 32 + 16], o_acc[1], LDS_OF, wmma::mem_row_major);
    __syncthreads();
    {
        int row  = tid >> 2;                 // 0..127
        int col0 = (tid & 3) << 4;
        int grow = qt * QROWS + row;
        int bb = bh >> 4, h = bh & 15;
        float inv_l = 1.0f / l_s[row];
        size_t base = ((size_t)bb * S_ + grow) * H_ + h * HD_ + col0;
#pragma unroll
        for (int c = 0; c < 16; c++)
            g_att[base + c] = __float2half_rn(Of[row * LDS_OF + col0 + c] * inv_l);
    }
}

// ---------------- launch -----------------------------------------------------
extern "C" void kernel_launch(void* const* d_in, const int* in_sizes, int n_in,
                              void* d_out, int out_size)
{
    const float* x     = (const float*)d_in[0];
    const float* w_qkv = (const float*)d_in[1];
    const float* b_qkv = (const float*)d_in[2];
    const float* w_out = (const float*)d_in[3];
    const float* b_out = (const float*)d_in[4];
    float* out = (float*)d_out;

    cudaFuncSetAttribute(gemm_fp16_kernel<0>,
                         cudaFuncAttributeMaxDynamicSharedMemorySize, GEMM_SMEM);
    cudaFuncSetAttribute(gemm_fp16_kernel<1>,
                         cudaFuncAttributeMaxDynamicSharedMemorySize, GEMM_SMEM);
    cudaFuncSetAttribute(attn_fp16_kernel,
                         cudaFuncAttributeMaxDynamicSharedMemorySize, ATTN_SMEM);

    tohalf_all_kernel<<<(N4_TOTAL + 255) / 256, 256>>>(
        (const float4*)x, (const float4*)w_qkv, (const float4*)w_out);

    dim3 g1((3 * H_) / BN, MR_ / BM);
    gemm_fp16_kernel<0><<<g1, 128, GEMM_SMEM>>>(b_qkv, nullptr, MR_, 3 * H_, H_);

    dim3 g2(S_ / QROWS, B_ * NH_);
    attn_fp16_kernel<<<g2, 512, ATTN_SMEM>>>();

    dim3 g3(H_ / BN, MR_ / BM);
    gemm_fp16_kernel<1><<<g3, 128, GEMM_SMEM>>>(b_out, out, MR_, H_, H_);
}